// round 10
// baseline (speedup 1.0000x reference)
#include <cuda_runtime.h>
#include <cstdint>

// Problem constants (fixed by the reference)
#define B_ 16
#define H_ 100
#define W_ 100
#define C_ 256
#define R_ 128
#define P_ 7
#define CELLS (P_ * P_)   // 49

__device__ __forceinline__ float4 lerp4(float4 a, float4 b, float4 c, float4 d,
                                        float fx, float fy)
{
    float4 o;
    float top, bot;
    top = a.x + (b.x - a.x) * fx;  bot = c.x + (d.x - c.x) * fx;  o.x = top + (bot - top) * fy;
    top = a.y + (b.y - a.y) * fx;  bot = c.y + (d.y - c.y) * fx;  o.y = top + (bot - top) * fy;
    top = a.z + (b.z - a.z) * fx;  bot = c.z + (d.z - c.z) * fx;  o.z = top + (bot - top) * fy;
    top = a.w + (b.w - a.w) * fx;  bot = c.w + (d.w - c.w) * fx;  o.w = top + (bot - top) * fy;
    return o;
}

__device__ __forceinline__ float4 ldcg4(const float4* p)
{
    float4 v;
    asm volatile("ld.global.cg.v4.f32 {%0,%1,%2,%3}, [%4];"
                 : "=f"(v.x), "=f"(v.y), "=f"(v.z), "=f"(v.w) : "l"(p));
    return v;
}

// TWO CTAs per ROI (channel halves), grid = 4096, 256 threads.
// Channel pairing: each thread owns TWO float4 groups (g, g+16) of its cell,
// so each iteration issues 8 independent LDG.128 from 4 shared base offsets
// (second load = +16 float4 immediate: no extra address registers -> ptxas
// keeps them batched). Layout: 16 cell-lanes x 16 channel threads; a warp
// covers 2 lanes, each corner load is 256B contiguous per lane (coalesced).
// launch_bounds(256,5) gives ~51 regs so all 8 float4 stay in flight.
// Phase 1: threads 0..48 build the per-cell bilinear table in smem.
// Phase 2: lane sweeps cells lane, lane+16, lane+32; cell 48 done by lane 0.
__global__ __launch_bounds__(256, 5) void roi_pool_kernel(
    const float* __restrict__ fm,   // [B, H, W, C]
    const int*   __restrict__ rois, // [B, R, 4]  (x, y, h, w)
    float*       __restrict__ out)  // [B, R, P, P, C]
{
    __shared__ int4   s_off[CELLS];   // float4-unit offsets of the 4 corners
    __shared__ float2 s_fr[CELLS];    // (fx, fy)

    const int roi_idx = blockIdx.x >> 1;        // b*R + r
    const int chalf   = blockIdx.x & 1;         // channel half 0/1
    const int b = roi_idx >> 7;                 // R_ = 128
    const int tid = threadIdx.x;

    if (tid < CELLS) {
        const int4 roi = __ldg((const int4*)(rois + (size_t)roi_idx * 4));
        const int x = roi.x, y = roi.y, h = roi.z, w = roi.w;

        const int py = tid / P_;
        const int px = tid - py * P_;

        // y axis: src = (py+0.5)/P * h - 0.5, clipped to [0, h-1]
        const float hf = (float)h;
        float sy = ((float)py + 0.5f) * (1.0f / P_) * hf - 0.5f;
        sy = fminf(fmaxf(sy, 0.0f), hf - 1.0f);
        int   y0 = (int)floorf(sy);
        const float fy = sy - (float)y0;
        y0 += y;
        const int y1 = min(y0 + 1, y + h - 1);

        // x axis
        const float wf = (float)w;
        float sx = ((float)px + 0.5f) * (1.0f / P_) * wf - 0.5f;
        sx = fminf(fmaxf(sx, 0.0f), wf - 1.0f);
        int   x0 = (int)floorf(sx);
        const float fx = sx - (float)x0;
        x0 += x;
        const int x1 = min(x0 + 1, x + w - 1);

        // offsets in float4 units (C_/4 = 64 per pixel row)
        s_off[tid] = make_int4((y0 * W_ + x0) * (C_ / 4),
                               (y0 * W_ + x1) * (C_ / 4),
                               (y1 * W_ + x0) * (C_ / 4),
                               (y1 * W_ + x1) * (C_ / 4));
        s_fr[tid] = make_float2(fx, fy);
    }
    __syncthreads();

    const int g0   = (chalf << 5) + (tid & 15); // first float4 group (0..63)
    const int lane = tid >> 4;                  // cell lane 0..15

    const float4* base  = (const float4*)(fm + (size_t)b * (H_ * W_ * C_)) + g0;
    float4*       obase = (float4*)(out + (size_t)roi_idx * (CELLS * C_)) + g0;

    // Tuple for the first cell.
    int4   off = s_off[lane];
    float2 fr  = s_fr[lane];

    // Lane covers cells lane, lane+16, lane+32 (3 cells).
    #pragma unroll
    for (int k = 0; k < 3; k++) {
        const int cell = lane + k * 16;

        // Prefetch next tuple before touching this cell's data.
        int4   noff;
        float2 nfr;
        if (k < 2) {
            noff = s_off[cell + 16];
            nfr  = s_fr[cell + 16];
        }

        // 8 independent loads: 4 corners x 2 channel groups (g0, g0+16).
        const float4 a0 = ldcg4(base + off.x);
        const float4 a1 = ldcg4(base + off.x + 16);
        const float4 b0 = ldcg4(base + off.y);
        const float4 b1 = ldcg4(base + off.y + 16);
        const float4 c0 = ldcg4(base + off.z);
        const float4 c1 = ldcg4(base + off.z + 16);
        const float4 d0 = ldcg4(base + off.w);
        const float4 d1 = ldcg4(base + off.w + 16);

        float4* op = obase + cell * (C_ / 4);
        __stcs(op,      lerp4(a0, b0, c0, d0, fr.x, fr.y));
        __stcs(op + 16, lerp4(a1, b1, c1, d1, fr.x, fr.y));

        if (k < 2) { off = noff; fr = nfr; }
    }

    // Remainder: cell 48 (lane 0 only).
    if (lane == 0) {
        const int4   roff = s_off[48];
        const float2 rfr  = s_fr[48];
        const float4 a0 = ldcg4(base + roff.x);
        const float4 a1 = ldcg4(base + roff.x + 16);
        const float4 b0 = ldcg4(base + roff.y);
        const float4 b1 = ldcg4(base + roff.y + 16);
        const float4 c0 = ldcg4(base + roff.z);
        const float4 c1 = ldcg4(base + roff.z + 16);
        const float4 d0 = ldcg4(base + roff.w);
        const float4 d1 = ldcg4(base + roff.w + 16);
        float4* op = obase + 48 * (C_ / 4);
        __stcs(op,      lerp4(a0, b0, c0, d0, rfr.x, rfr.y));
        __stcs(op + 16, lerp4(a1, b1, c1, d1, rfr.x, rfr.y));
    }
}

extern "C" void kernel_launch(void* const* d_in, const int* in_sizes, int n_in,
                              void* d_out, int out_size)
{
    const float* fm   = (const float*)d_in[0];
    const int*   rois = (const int*)d_in[1];
    float*       out  = (float*)d_out;

    roi_pool_kernel<<<B_ * R_ * 2, 256>>>(fm, rois, out);
}